// round 3
// baseline (speedup 1.0000x reference)
#include <cuda_runtime.h>
#include <math.h>

#define DD 128
#define WIN 15
#define WW (2*WIN+1)
#define MAXB 4
#define MAXS 4096
#define RPB 8                 // band rows per block
#define TROWS (RPB + 2*WIN)   // 38 smem rows

__device__ float g_invnorm[MAXB*MAXS];
__device__ int   g_spk[MAXB*MAXS];
__device__ float g_band[(size_t)MAXB*MAXS*WW];
__device__ float g_dinv[MAXB*MAXS];

// ---------------- Kernel 1: inv-norms (8 threads/row) + speaker argmax ----------------
__global__ __launch_bounds__(256)
void prep_kernel(const float* __restrict__ x,
                 const float* __restrict__ qmask,
                 int B, int S, int NSPK) {
    int t = blockIdx.x * blockDim.x + threadIdx.x;
    int row = t >> 3;          // 8 threads per row
    int sub = t & 7;
    if (row >= B * S) return;

    const float4* xr = (const float4*)(x + (size_t)row * DD);
    float ss = 0.f;
#pragma unroll
    for (int k = 0; k < 4; k++) {
        float4 v = xr[sub * 4 + k];
        ss += v.x * v.x + v.y * v.y + v.z * v.z + v.w * v.w;
    }
#pragma unroll
    for (int off = 4; off; off >>= 1)
        ss += __shfl_xor_sync(0xffffffffu, ss, off);

    if (sub == 0)
        g_invnorm[row] = 1.f / fmaxf(sqrtf(ss), 1e-8f);

    if (sub == 1) {
        int b = row / S, s = row % S;
        const float* q = qmask + ((size_t)s * B + b) * NSPK;
        float best = q[0];
        int bi = 0;
        for (int k = 1; k < NSPK; k++) {
            float v = q[k];
            if (v > best) { best = v; bi = k; }   // strict > = JAX first-max
        }
        g_spk[row] = bi;
    }
}

// ---------------- Kernel 2: band values + dinv, smem-tiled ----------------
__global__ __launch_bounds__(256)
void band_kernel(const float* __restrict__ x,
                 const int* __restrict__ dia_len,
                 int B, int S) {
    __shared__ float sx[TROWS * DD];
    __shared__ int   sspk[TROWS];

    int b  = blockIdx.y;
    int i0 = blockIdx.x * RPB;
    int base = b * S;
    int len = dia_len[b];
    int gr0 = i0 - WIN;

    float4* sx4 = (float4*)sx;
    const float4* x4 = (const float4*)(x + (size_t)base * DD);
    for (int idx = threadIdx.x; idx < TROWS * (DD/4); idx += blockDim.x) {
        int r = idx >> 5;
        int q = idx & 31;
        int gr = gr0 + r;
        float4 v = {0.f, 0.f, 0.f, 0.f};
        if (gr >= 0 && gr < S) {
            v = x4[(size_t)gr * 32 + q];
            float inv = g_invnorm[base + gr];
            v.x *= inv; v.y *= inv; v.z *= inv; v.w *= inv;
        }
        sx4[idx] = v;
    }
    if (threadIdx.x < TROWS) {
        int gr = gr0 + threadIdx.x;
        sspk[threadIdx.x] = (gr >= 0 && gr < S) ? g_spk[base + gr] : -1;
    }
    __syncthreads();

    int w = threadIdx.x >> 5;
    int lane = threadIdx.x & 31;
    int i = i0 + w;
    if (i >= S) return;
    int li = WIN + w;
    bool valid_i = (i < len);
    int spk_i = sspk[li];

    float4 xi = ((float4*)(sx + li * DD))[lane];

    int cnt = 0;
    if (valid_i) {
#pragma unroll
        for (int jj = 0; jj < WW; jj++) {
            int j = i - WIN + jj;
            if (j >= 0 && j < len && sspk[w + jj] == spk_i) cnt++;
        }
    }

    float deg = 0.f;
    float* bp = g_band + (size_t)(base + i) * WW;
#pragma unroll
    for (int jj = 0; jj < WW; jj++) {
        int j = i - WIN + jj;
        float a = 0.f;
        if (valid_i && j >= 0 && j < len) {
            float4 xj = ((float4*)(sx + (w + jj) * DD))[lane];
            float dot = xi.x * xj.x + xi.y * xj.y + xi.z * xj.z + xi.w * xj.w;
#pragma unroll
            for (int off = 16; off; off >>= 1)
                dot += __shfl_xor_sync(0xffffffffu, dot, off);
            float c = fminf(fmaxf(dot, -1.f), 1.f);
            float wgt = 1.f - acosf(c) * 0.31830988618379067f;
            bool same = (sspk[w + jj] == spk_i);
            a = wgt * ((cnt > 1 && same) ? 2.f : 1.f);
            deg += a;
        }
        if (lane == jj) bp[jj] = a;
    }
    if (lane == 0)
        g_dinv[base + i] = (deg > 0.f) ? rsqrtf(deg) : 1.f;
}

// ---------------- Kernel 3: scatter normalized band into zeroed output ----------------
__global__ __launch_bounds__(256)
void scatter_kernel(float* __restrict__ out, int B, int S) {
    int warp = (blockIdx.x * blockDim.x + threadIdx.x) >> 5;
    int lane = threadIdx.x & 31;
    if (warp >= B * S || lane >= WW) return;
    int b = warp / S, i = warp % S;
    int j = i - WIN + lane;
    if (j < 0 || j >= S) return;
    float a = g_band[(size_t)warp * WW + lane];
    out[(size_t)warp * S + j] = a * g_dinv[warp] * g_dinv[b * S + j];
}

extern "C" void kernel_launch(void* const* d_in, const int* in_sizes, int n_in,
                              void* d_out, int out_size) {
    const float* x       = (const float*)d_in[0];
    const float* qmask   = (const float*)d_in[1];
    const int*   dia_len = (const int*)d_in[2];
    float* out = (float*)d_out;

    int B = in_sizes[2];
    int S = in_sizes[0] / (B * DD);
    int NSPK = in_sizes[1] / (B * S);
    int n = B * S;

    // one-time side-stream + fork/join events (no device-memory allocation)
    static cudaStream_t s2 = nullptr;
    static cudaEvent_t e_fork = nullptr, e_join = nullptr;
    if (!s2) {
        cudaStreamCreateWithFlags(&s2, cudaStreamNonBlocking);
        cudaEventCreateWithFlags(&e_fork, cudaEventDisableTiming);
        cudaEventCreateWithFlags(&e_join, cudaEventDisableTiming);
    }

    // fork: side stream computes band while main stream zeroes 256MB
    cudaEventRecord(e_fork, 0);
    cudaStreamWaitEvent(s2, e_fork, 0);

    prep_kernel<<<(n * 8 + 255) / 256, 256, 0, s2>>>(x, qmask, B, S, NSPK);
    dim3 bgrid((S + RPB - 1) / RPB, B);
    band_kernel<<<bgrid, 256, 0, s2>>>(x, dia_len, B, S);
    cudaEventRecord(e_join, s2);

    cudaMemsetAsync(out, 0, (size_t)out_size * sizeof(float), 0);

    // join: scatter band values over the zeros
    cudaStreamWaitEvent(0, e_join, 0);
    scatter_kernel<<<(n * 32 + 255) / 256, 256>>>(out, B, S);
}

// round 4
// speedup vs baseline: 1.0464x; 1.0464x over previous
#include <cuda_runtime.h>
#include <math.h>

#define DD 128
#define WIN 15
#define WW (2*WIN+1)
#define MAXB 4
#define MAXS 4096
#define RPB 8                 // band rows per block
#define TROWS (RPB + 2*WIN)   // 38 smem rows

__device__ float g_invnorm[MAXB*MAXS];
__device__ int   g_spk[MAXB*MAXS];
__device__ float g_band[(size_t)MAXB*MAXS*WW];
__device__ float g_dinv[MAXB*MAXS];

// ---------------- Kernel 0: max-bandwidth zero fill ----------------
__global__ __launch_bounds__(256)
void zero_kernel(float4* __restrict__ out, size_t n4) {
    size_t stride = (size_t)gridDim.x * blockDim.x;
    size_t i = (size_t)blockIdx.x * blockDim.x + threadIdx.x;
    const float4 z = {0.f, 0.f, 0.f, 0.f};
    for (; i < n4; i += stride)
        __stcs(&out[i], z);
}

// ---------------- Kernel 1: inv-norms (8 threads/row) + speaker argmax ----------------
__global__ __launch_bounds__(256)
void prep_kernel(const float* __restrict__ x,
                 const float* __restrict__ qmask,
                 int B, int S, int NSPK) {
    int t = blockIdx.x * blockDim.x + threadIdx.x;
    int row = t >> 3;
    int sub = t & 7;
    if (row >= B * S) return;

    const float4* xr = (const float4*)(x + (size_t)row * DD);
    float ss = 0.f;
#pragma unroll
    for (int k = 0; k < 4; k++) {
        float4 v = xr[sub * 4 + k];
        ss += v.x * v.x + v.y * v.y + v.z * v.z + v.w * v.w;
    }
#pragma unroll
    for (int off = 4; off; off >>= 1)
        ss += __shfl_xor_sync(0xffffffffu, ss, off);

    if (sub == 0)
        g_invnorm[row] = 1.f / fmaxf(sqrtf(ss), 1e-8f);

    if (sub == 1) {
        int b = row / S, s = row % S;
        const float* q = qmask + ((size_t)s * B + b) * NSPK;
        float best = q[0];
        int bi = 0;
        for (int k = 1; k < NSPK; k++) {
            float v = q[k];
            if (v > best) { best = v; bi = k; }   // strict > = JAX first-max
        }
        g_spk[row] = bi;
    }
}

// ---------------- Kernel 2: band values + dinv, smem-tiled ----------------
__global__ __launch_bounds__(256)
void band_kernel(const float* __restrict__ x,
                 const int* __restrict__ dia_len,
                 int B, int S) {
    __shared__ float sx[TROWS * DD];
    __shared__ int   sspk[TROWS];

    int b  = blockIdx.y;
    int i0 = blockIdx.x * RPB;
    int base = b * S;
    int len = dia_len[b];
    int gr0 = i0 - WIN;

    float4* sx4 = (float4*)sx;
    const float4* x4 = (const float4*)(x + (size_t)base * DD);
    for (int idx = threadIdx.x; idx < TROWS * (DD/4); idx += blockDim.x) {
        int r = idx >> 5;
        int q = idx & 31;
        int gr = gr0 + r;
        float4 v = {0.f, 0.f, 0.f, 0.f};
        if (gr >= 0 && gr < S) {
            v = x4[(size_t)gr * 32 + q];
            float inv = g_invnorm[base + gr];
            v.x *= inv; v.y *= inv; v.z *= inv; v.w *= inv;
        }
        sx4[idx] = v;
    }
    if (threadIdx.x < TROWS) {
        int gr = gr0 + threadIdx.x;
        sspk[threadIdx.x] = (gr >= 0 && gr < S) ? g_spk[base + gr] : -1;
    }
    __syncthreads();

    int w = threadIdx.x >> 5;
    int lane = threadIdx.x & 31;
    int i = i0 + w;
    if (i >= S) return;
    int li = WIN + w;
    bool valid_i = (i < len);
    int spk_i = sspk[li];

    float4 xi = ((float4*)(sx + li * DD))[lane];

    int cnt = 0;
    if (valid_i) {
#pragma unroll
        for (int jj = 0; jj < WW; jj++) {
            int j = i - WIN + jj;
            if (j >= 0 && j < len && sspk[w + jj] == spk_i) cnt++;
        }
    }

    float deg = 0.f;
    float* bp = g_band + (size_t)(base + i) * WW;
#pragma unroll
    for (int jj = 0; jj < WW; jj++) {
        int j = i - WIN + jj;
        float a = 0.f;
        if (valid_i && j >= 0 && j < len) {
            float4 xj = ((float4*)(sx + (w + jj) * DD))[lane];
            float dot = xi.x * xj.x + xi.y * xj.y + xi.z * xj.z + xi.w * xj.w;
#pragma unroll
            for (int off = 16; off; off >>= 1)
                dot += __shfl_xor_sync(0xffffffffu, dot, off);
            float c = fminf(fmaxf(dot, -1.f), 1.f);
            float wgt = 1.f - acosf(c) * 0.31830988618379067f;
            bool same = (sspk[w + jj] == spk_i);
            a = wgt * ((cnt > 1 && same) ? 2.f : 1.f);
            deg += a;
        }
        if (lane == jj) bp[jj] = a;
    }
    if (lane == 0)
        g_dinv[base + i] = (deg > 0.f) ? rsqrtf(deg) : 1.f;
}

// ---------------- Kernel 3: scatter normalized band into zeroed output ----------------
__global__ __launch_bounds__(256)
void scatter_kernel(float* __restrict__ out, int B, int S) {
    int warp = (blockIdx.x * blockDim.x + threadIdx.x) >> 5;
    int lane = threadIdx.x & 31;
    if (warp >= B * S || lane >= WW) return;
    int b = warp / S, i = warp % S;
    int j = i - WIN + lane;
    if (j < 0 || j >= S) return;
    float a = g_band[(size_t)warp * WW + lane];
    out[(size_t)warp * S + j] = a * g_dinv[warp] * g_dinv[b * S + j];
}

extern "C" void kernel_launch(void* const* d_in, const int* in_sizes, int n_in,
                              void* d_out, int out_size) {
    const float* x       = (const float*)d_in[0];
    const float* qmask   = (const float*)d_in[1];
    const int*   dia_len = (const int*)d_in[2];
    float* out = (float*)d_out;

    int B = in_sizes[2];
    int S = in_sizes[0] / (B * DD);
    int NSPK = in_sizes[1] / (B * S);
    int n = B * S;

    static cudaStream_t s2 = nullptr;
    static cudaEvent_t e_fork = nullptr, e_join = nullptr;
    if (!s2) {
        cudaStreamCreateWithFlags(&s2, cudaStreamNonBlocking);
        cudaEventCreateWithFlags(&e_fork, cudaEventDisableTiming);
        cudaEventCreateWithFlags(&e_join, cudaEventDisableTiming);
    }

    // fork: side stream computes band while main stream zeroes 256MB
    cudaEventRecord(e_fork, 0);
    cudaStreamWaitEvent(s2, e_fork, 0);

    prep_kernel<<<(n * 8 + 255) / 256, 256, 0, s2>>>(x, qmask, B, S, NSPK);
    dim3 bgrid((S + RPB - 1) / RPB, B);
    band_kernel<<<bgrid, 256, 0, s2>>>(x, dia_len, B, S);
    cudaEventRecord(e_join, s2);

    size_t n4 = (size_t)out_size / 4;   // out_size is element count (fp32), /4 per float4
    zero_kernel<<<2368, 256>>>((float4*)out, n4);

    // join: scatter band values over the zeros
    cudaStreamWaitEvent(0, e_join, 0);
    scatter_kernel<<<(n * 32 + 255) / 256, 256>>>(out, B, S);
}